// round 9
// baseline (speedup 1.0000x reference)
#include <cuda_runtime.h>
#include <cuda_bf16.h>
#include <cstring>
#include <cstdint>

#define N_SRC1 500000
#define N_DST1 100000
#define E1     1500000
#define N_DST2 20000
#define E2     200000
#define IN_F   128
#define H_F    256
#define N_CLS  47

#define NB1 98   // ceil(N_DST1/1024)
#define NB2 20   // ceil(N_DST2/1024)

// ---------------- scratch (device globals: no allocs allowed) ----------------
__device__ float g_hn1[(size_t)N_DST1 * IN_F];
__device__ float g_h[(size_t)N_DST1 * H_F];
__device__ float g_hn2[(size_t)N_DST2 * H_F];

__device__ __nv_bfloat16 g_Bhi[256 * 256];   // W1 split hi, [n][k]
__device__ __nv_bfloat16 g_Blo[256 * 256];   // W1 split lo, [n][k]

// zero-initialized at module load; re-zeroed by gemm2's tail every replay
__device__ int g_cnt1[N_DST1];
__device__ int g_cnt2[N_DST2];

__device__ int g_row1[N_DST1 + 1];
__device__ int g_cur1[N_DST1];
__device__ int g_eidx1[E1];

__device__ int g_row2[N_DST2 + 1];
__device__ int g_cur2[N_DST2];
__device__ int g_eidx2[E2];

__device__ int g_bsum1[128];
__device__ int g_bsum2[128];
__device__ int g_boff1[128];
__device__ int g_boff2[128];

// ---------------- helpers ----------------
__device__ __forceinline__ uint32_t sptr(const void* p) {
    return (uint32_t)__cvta_generic_to_shared(p);
}

__device__ __forceinline__ void fma2(unsigned long long& d, unsigned long long a,
                                     unsigned long long b) {
    asm("fma.rn.f32x2 %0, %1, %2, %0;" : "+l"(d) : "l"(a), "l"(b));
}
__device__ __forceinline__ unsigned long long dup2(float v) {
    unsigned long long r;
    asm("mov.b64 %0, {%1, %1};" : "=l"(r) : "f"(v));
    return r;
}
__device__ __forceinline__ float2 unpack2(unsigned long long v) {
    float2 f;
    memcpy(&f, &v, 8);
    return f;
}

__device__ __forceinline__ void split8(float4 v0, float4 v1, uint4& hi, uint4& lo) {
    float f[8] = {v0.x, v0.y, v0.z, v0.w, v1.x, v1.y, v1.z, v1.w};
    __nv_bfloat16 h[8], l[8];
    #pragma unroll
    for (int i = 0; i < 8; i++) {
        h[i] = __float2bfloat16_rn(f[i]);
        l[i] = __float2bfloat16_rn(f[i] - __bfloat162float(h[i]));
    }
    memcpy(&hi, h, 16);
    memcpy(&lo, l, 16);
}

__device__ __forceinline__ void ldm_x4(uint32_t* r, uint32_t addr) {
    asm volatile("ldmatrix.sync.aligned.m8n8.x4.shared.b16 {%0,%1,%2,%3}, [%4];"
                 : "=r"(r[0]), "=r"(r[1]), "=r"(r[2]), "=r"(r[3]) : "r"(addr));
}
__device__ __forceinline__ void mma16816(float* d, const uint32_t* a, uint32_t b0, uint32_t b1) {
    asm volatile(
        "mma.sync.aligned.m16n8k16.row.col.f32.bf16.bf16.f32 "
        "{%0,%1,%2,%3}, {%4,%5,%6,%7}, {%8,%9}, {%0,%1,%2,%3};"
        : "+f"(d[0]), "+f"(d[1]), "+f"(d[2]), "+f"(d[3])
        : "r"(a[0]), "r"(a[1]), "r"(a[2]), "r"(a[3]), "r"(b0), "r"(b1));
}

// ---------------- W1 split + transpose: [k][n] fp32 -> [n][k] bf16 hi/lo ----------------
__global__ void k_splitW(const float* __restrict__ Ws, const float* __restrict__ Wn) {
    int i = blockIdx.x * blockDim.x + threadIdx.x;
    if (i >= 256 * 256) return;
    int k = i >> 8;
    int n = i & 255;
    float w = (k < 128) ? Ws[k * 256 + n] : Wn[(k - 128) * 256 + n];
    __nv_bfloat16 h = __float2bfloat16_rn(w);
    __nv_bfloat16 l = __float2bfloat16_rn(w - __bfloat162float(h));
    g_Bhi[n * 256 + k] = h;
    g_Blo[n * 256 + k] = l;
}

// ---------------- CSR build (counts pre-zeroed: module init / gemm2 tail) ----------------
__global__ void k_count(const int* __restrict__ d1, const int* __restrict__ d2) {
    int i = blockIdx.x * blockDim.x + threadIdx.x;
    if (i < E1) atomicAdd(&g_cnt1[d1[i]], 1);
    if (i < E2) atomicAdd(&g_cnt2[d2[i]], 1);
}

__global__ void k_scanA() {
    __shared__ int s[1024];
    int b = blockIdx.x;
    const int* cnt; int n; int* bsum; int bb;
    if (b < NB1) { cnt = g_cnt1; n = N_DST1; bsum = g_bsum1; bb = b; }
    else         { cnt = g_cnt2; n = N_DST2; bsum = g_bsum2; bb = b - NB1; }
    int i = bb * 1024 + threadIdx.x;
    int v = (i < n) ? cnt[i] : 0;
    s[threadIdx.x] = v;
    __syncthreads();
    #pragma unroll
    for (int off = 512; off > 0; off >>= 1) {
        if (threadIdx.x < off) s[threadIdx.x] += s[threadIdx.x + off];
        __syncthreads();
    }
    if (threadIdx.x == 0) bsum[bb] = s[0];
}

__global__ void k_scanB() {
    __shared__ int s1[128];
    __shared__ int s2[128];
    int t = threadIdx.x;
    if (t < 128) s1[t] = (t < NB1) ? g_bsum1[t] : 0;
    else         { int u = t - 128; s2[u] = (u < NB2) ? g_bsum2[u] : 0; }
    __syncthreads();
    #pragma unroll
    for (int off = 1; off < 128; off <<= 1) {
        int v;
        if (t < 128) v = (t >= off) ? s1[t - off] : 0;
        else         { int u = t - 128; v = (u >= off) ? s2[u - off] : 0; }
        __syncthreads();
        if (t < 128) s1[t] += v;
        else         s2[t - 128] += v;
        __syncthreads();
    }
    if (t < 128) { if (t < NB1) g_boff1[t] = (t ? s1[t - 1] : 0); }
    else         { int u = t - 128; if (u < NB2) g_boff2[u] = (u ? s2[u - 1] : 0); }
}

__global__ void k_scanC() {
    __shared__ int s[1024];
    int b = blockIdx.x;
    const int* cnt; int n; int* row; int* cur; int boff; int bb; int etot;
    if (b < NB1) { cnt = g_cnt1; n = N_DST1; row = g_row1; cur = g_cur1; bb = b;       boff = g_boff1[bb]; etot = E1; }
    else         { cnt = g_cnt2; n = N_DST2; row = g_row2; cur = g_cur2; bb = b - NB1; boff = g_boff2[bb]; etot = E2; }
    int t = threadIdx.x;
    int i = bb * 1024 + t;
    int v = (i < n) ? cnt[i] : 0;
    s[t] = v;
    __syncthreads();
    #pragma unroll
    for (int off = 1; off < 1024; off <<= 1) {
        int u = (t >= off) ? s[t - off] : 0;
        __syncthreads();
        s[t] += u;
        __syncthreads();
    }
    int excl = boff + s[t] - v;
    if (i < n) { row[i] = excl; cur[i] = excl; }
    if (i == n - 1) row[n] = etot;
}

__global__ void k_fill(const int* __restrict__ s1, const int* __restrict__ d1,
                       const int* __restrict__ s2, const int* __restrict__ d2) {
    int i = blockIdx.x * blockDim.x + threadIdx.x;
    if (i < E1) {
        int p = atomicAdd(&g_cur1[d1[i]], 1);
        g_eidx1[p] = s1[i];
    }
    if (i < E2) {
        int p = atomicAdd(&g_cur2[d2[i]], 1);
        g_eidx2[p] = s2[i];
    }
}

// ---------------- aggregation (warp per dst node) ----------------
__global__ void k_agg1(const float4* __restrict__ x4) {
    int w = (blockIdx.x * blockDim.x + threadIdx.x) >> 5;
    int lane = threadIdx.x & 31;
    if (w >= N_DST1) return;
    int e0 = g_row1[w], e1 = g_row1[w + 1];
    float4 acc = make_float4(0.f, 0.f, 0.f, 0.f);
    int e = e0;
    for (; e + 3 < e1; e += 4) {
        int sa = g_eidx1[e];
        int sb = g_eidx1[e + 1];
        int sc = g_eidx1[e + 2];
        int sd = g_eidx1[e + 3];
        float4 va = __ldg(&x4[(size_t)sa * 32 + lane]);
        float4 vb = __ldg(&x4[(size_t)sb * 32 + lane]);
        float4 vc = __ldg(&x4[(size_t)sc * 32 + lane]);
        float4 vd = __ldg(&x4[(size_t)sd * 32 + lane]);
        acc.x += (va.x + vb.x) + (vc.x + vd.x);
        acc.y += (va.y + vb.y) + (vc.y + vd.y);
        acc.z += (va.z + vb.z) + (vc.z + vd.z);
        acc.w += (va.w + vb.w) + (vc.w + vd.w);
    }
    for (; e < e1; e++) {
        int sa = g_eidx1[e];
        float4 va = __ldg(&x4[(size_t)sa * 32 + lane]);
        acc.x += va.x; acc.y += va.y; acc.z += va.z; acc.w += va.w;
    }
    float inv = 1.0f / fmaxf((float)(e1 - e0), 1.0f);
    acc.x *= inv; acc.y *= inv; acc.z *= inv; acc.w *= inv;
    ((float4*)g_hn1)[(size_t)w * 32 + lane] = acc;
}

__global__ void k_agg2() {
    int w = (blockIdx.x * blockDim.x + threadIdx.x) >> 5;
    int lane = threadIdx.x & 31;
    if (w >= N_DST2) return;
    const float4* h4 = (const float4*)g_h;
    int e0 = g_row2[w], e1 = g_row2[w + 1];
    float4 a0 = make_float4(0.f, 0.f, 0.f, 0.f);
    float4 a1 = make_float4(0.f, 0.f, 0.f, 0.f);
    for (int e = e0; e < e1; e++) {
        int s = g_eidx2[e];
        float4 v0 = __ldg(&h4[(size_t)s * 64 + lane]);
        float4 v1 = __ldg(&h4[(size_t)s * 64 + lane + 32]);
        a0.x += v0.x; a0.y += v0.y; a0.z += v0.z; a0.w += v0.w;
        a1.x += v1.x; a1.y += v1.y; a1.z += v1.z; a1.w += v1.w;
    }
    float inv = 1.0f / fmaxf((float)(e1 - e0), 1.0f);
    a0.x *= inv; a0.y *= inv; a0.z *= inv; a0.w *= inv;
    a1.x *= inv; a1.y *= inv; a1.z *= inv; a1.w *= inv;
    ((float4*)g_hn2)[(size_t)w * 64 + lane] = a0;
    ((float4*)g_hn2)[(size_t)w * 64 + lane + 32] = a1;
}

// ---------------- layer-1 GEMM halves (tensor cores, bf16 hi/lo split) ----------------
// Self half:  C_partial = x @ W'[0:128]   (raw partial, no bias/relu)
// Neigh half: C = relu(C_partial + hn1 @ W'[128:256] + b1)
// Each: block 128x128, 8 warps (4m x 2n), warp tile 32x64, 8 k-chunks of 16 fp32.
#define APITCH 24   // bf16 elements per smem row (16 data + 8 pad = 48B)

struct G1Frag {
    float acc[2][8][4];
};

// Common mainloop for one half. kc_base: 0 (self, A from x) or 8 (neigh, A from g_hn1).
template <int KC_BASE>
__device__ __forceinline__ void gemm1_mainloop(const float* __restrict__ Asrc,
                                               int m0, int n0, G1Frag& F,
                                               __nv_bfloat16* sAhi, __nv_bfloat16* sAlo,
                                               __nv_bfloat16* sBhi, __nv_bfloat16* sBlo) {
    int t = threadIdx.x;
    int lane = t & 31;
    int wid = t >> 5;
    int wm = (wid & 3) * 32;
    int wn = (wid >> 2) * 64;

    int lrow = t >> 1;
    int lq   = (t & 1) << 3;
    int grow = m0 + lrow;

    uint32_t aHi = sptr(sAhi), aLo = sptr(sAlo), bHi = sptr(sBhi), bLo = sptr(sBlo);

    int a_r = (lane & 15);
    int a_c = (lane >> 4) << 3;
    int b_r = (lane & 7) + ((lane >> 4) << 3);
    int b_c = ((lane >> 3) & 1) << 3;

    float4 pA0, pA1;
    uint4 pBh, pBl;

    auto ldA = [&](int kc) {   // kc local 0..7
        if (grow < N_DST1) {
            const float* p = Asrc + (size_t)grow * IN_F + kc * 16 + lq;
            pA0 = *(const float4*)p;
            pA1 = *(const float4*)(p + 4);
        } else {
            pA0 = make_float4(0.f, 0.f, 0.f, 0.f);
            pA1 = make_float4(0.f, 0.f, 0.f, 0.f);
        }
    };
    auto ldB = [&](int kc) {   // absolute k = (KC_BASE+kc)*16
        size_t off = (size_t)(n0 + lrow) * 256 + (KC_BASE + kc) * 16 + lq;
        pBh = *(const uint4*)(g_Bhi + off);
        pBl = *(const uint4*)(g_Blo + off);
    };
    auto sts = [&]() {
        uint4 hi, lo;
        split8(pA0, pA1, hi, lo);
        *(uint4*)&sAhi[lrow * APITCH + lq] = hi;
        *(uint4*)&sAlo[lrow * APITCH + lq] = lo;
        *(uint4*)&sBhi[lrow * APITCH + lq] = pBh;
        *(uint4*)&sBlo[lrow * APITCH + lq] = pBl;
    };
    auto pass = [&](uint32_t abase, uint32_t bbase) {
        uint32_t a[2][4];
        #pragma unroll
        for (int mf = 0; mf < 2; mf++)
            ldm_x4(a[mf], abase + ((wm + mf * 16 + a_r) * APITCH + a_c) * 2);
        #pragma unroll
        for (int pair = 0; pair < 4; pair++) {
            uint32_t bb[4];
            ldm_x4(bb, bbase + ((wn + pair * 16 + b_r) * APITCH + b_c) * 2);
            #pragma unroll
            for (int mf = 0; mf < 2; mf++) {
                mma16816(F.acc[mf][pair * 2],     a[mf], bb[0], bb[1]);
                mma16816(F.acc[mf][pair * 2 + 1], a[mf], bb[2], bb[3]);
            }
        }
    };

    ldA(0);
    ldB(0);
    for (int kc = 0; kc < 8; kc++) {
        sts();
        __syncthreads();
        if (kc < 7) { ldA(kc + 1); ldB(kc + 1); }
        pass(aHi, bHi);
        pass(aLo, bHi);
        pass(aHi, bLo);
        __syncthreads();
    }
}

__global__ __launch_bounds__(256, 2) void k_gemm1_self(const float* __restrict__ x) {
    __shared__ __nv_bfloat16 sAhi[128 * APITCH];
    __shared__ __nv_bfloat16 sAlo[128 * APITCH];
    __shared__ __nv_bfloat16 sBhi[128 * APITCH];
    __shared__ __nv_bfloat16 sBlo[128 * APITCH];
    int m0 = blockIdx.y * 128;
    int n0 = blockIdx.x * 128;
    G1Frag F;
    #pragma unroll
    for (int i = 0; i < 2; i++)
        #pragma unroll
        for (int j = 0; j < 8; j++)
            #pragma unroll
            for (int q = 0; q < 4; q++) F.acc[i][j][q] = 0.f;

    gemm1_mainloop<0>(x, m0, n0, F, sAhi, sAlo, sBhi, sBlo);

    int lane = threadIdx.x & 31;
    int wid = threadIdx.x >> 5;
    int wm = (wid & 3) * 32;
    int wn = (wid >> 2) * 64;
    #pragma unroll
    for (int mf = 0; mf < 2; mf++) {
        int gr0 = m0 + wm + mf * 16 + (lane >> 2);
        int gr1 = gr0 + 8;
        #pragma unroll
        for (int nf = 0; nf < 8; nf++) {
            int gn = n0 + wn + nf * 8 + ((lane & 3) << 1);
            float* d = F.acc[mf][nf];
            if (gr0 < N_DST1)
                *(float2*)&g_h[(size_t)gr0 * H_F + gn] = make_float2(d[0], d[1]);
            if (gr1 < N_DST1)
                *(float2*)&g_h[(size_t)gr1 * H_F + gn] = make_float2(d[2], d[3]);
        }
    }
}

__global__ __launch_bounds__(256, 2) void k_gemm1_neigh(const float* __restrict__ b1) {
    __shared__ __nv_bfloat16 sAhi[128 * APITCH];
    __shared__ __nv_bfloat16 sAlo[128 * APITCH];
    __shared__ __nv_bfloat16 sBhi[128 * APITCH];
    __shared__ __nv_bfloat16 sBlo[128 * APITCH];
    int m0 = blockIdx.y * 128;
    int n0 = blockIdx.x * 128;
    G1Frag F;
    #pragma unroll
    for (int i = 0; i < 2; i++)
        #pragma unroll
        for (int j = 0; j < 8; j++)
            #pragma unroll
            for (int q = 0; q < 4; q++) F.acc[i][j][q] = 0.f;

    gemm1_mainloop<8>(g_hn1, m0, n0, F, sAhi, sAlo, sBhi, sBlo);

    int lane = threadIdx.x & 31;
    int wid = threadIdx.x >> 5;
    int wm = (wid & 3) * 32;
    int wn = (wid >> 2) * 64;
    #pragma unroll
    for (int mf = 0; mf < 2; mf++) {
        int gr0 = m0 + wm + mf * 16 + (lane >> 2);
        int gr1 = gr0 + 8;
        #pragma unroll
        for (int nf = 0; nf < 8; nf++) {
            int gn = n0 + wn + nf * 8 + ((lane & 3) << 1);
            float bx = b1[gn];
            float by = b1[gn + 1];
            float* d = F.acc[mf][nf];
            if (gr0 < N_DST1) {
                float2* p = (float2*)&g_h[(size_t)gr0 * H_F + gn];
                float2 o = *p;
                *p = make_float2(fmaxf(o.x + d[0] + bx, 0.f), fmaxf(o.y + d[1] + by, 0.f));
            }
            if (gr1 < N_DST1) {
                float2* p = (float2*)&g_h[(size_t)gr1 * H_F + gn];
                float2 o = *p;
                *p = make_float2(fmaxf(o.x + d[2] + bx, 0.f), fmaxf(o.y + d[3] + by, 0.f));
            }
        }
    }
}

// ---------------- layer-2 GEMM + count-rezero tail ----------------
__global__ __launch_bounds__(256) void k_gemm2(const float* __restrict__ Ws2,
                                               const float* __restrict__ Wn2,
                                               const float* __restrict__ b2,
                                               float* __restrict__ out) {
    __shared__ float As[32][128];
    __shared__ float Bs[32][48];
    int t = threadIdx.x;
    int m0 = blockIdx.x * 128;
    int r0 = (t >> 3) * 4;
    int c0 = (t & 7) * 6;

    unsigned long long acc[4][3];
    #pragma unroll
    for (int i = 0; i < 4; i++)
        #pragma unroll
        for (int j = 0; j < 3; j++) acc[i][j] = 0ull;

    for (int kt = 0; kt < 16; kt++) {
        const float* Ab = (kt < 8) ? g_h : g_hn2;
        const float* Bb = (kt < 8) ? Ws2 : Wn2;
        int koff = (kt < 8) ? kt * 32 : (kt - 8) * 32;

        {
            int row = t >> 1;
            int grow = m0 + row;
            #pragma unroll
            for (int j = 0; j < 4; j++) {
                int kq = (t & 1) * 16 + j * 4;
                float4 v = make_float4(0.f, 0.f, 0.f, 0.f);
                if (grow < N_DST2) v = *(const float4*)(Ab + (size_t)grow * H_F + koff + kq);
                As[kq + 0][row] = v.x;
                As[kq + 1][row] = v.y;
                As[kq + 2][row] = v.z;
                As[kq + 3][row] = v.w;
            }
        }
        for (int l = t; l < 32 * N_CLS; l += 256) {
            int k = l / N_CLS;
            int c = l - k * N_CLS;
            Bs[k][c] = Bb[(size_t)(koff + k) * N_CLS + c];
        }
        __syncthreads();
        #pragma unroll
        for (int k = 0; k < 32; k++) {
            float4 a = *(const float4*)&As[k][r0];
            float av[4] = {a.x, a.y, a.z, a.w};
            unsigned long long bp[3];
            bp[0] = *(const unsigned long long*)&Bs[k][c0];
            bp[1] = *(const unsigned long long*)&Bs[k][c0 + 2];
            bp[2] = *(const unsigned long long*)&Bs[k][c0 + 4];
            #pragma unroll
            for (int i = 0; i < 4; i++) {
                unsigned long long ad = dup2(av[i]);
                #pragma unroll
                for (int j = 0; j < 3; j++) fma2(acc[i][j], ad, bp[j]);
            }
        }
        __syncthreads();
    }

    #pragma unroll
    for (int i = 0; i < 4; i++) {
        int row = m0 + r0 + i;
        if (row < N_DST2) {
            #pragma unroll
            for (int j = 0; j < 3; j++) {
                float2 v = unpack2(acc[i][j]);
                int c = c0 + 2 * j;
                if (c < N_CLS)     out[(size_t)row * N_CLS + c]     = v.x + b2[c];
                if (c + 1 < N_CLS) out[(size_t)row * N_CLS + c + 1] = v.y + b2[c + 1];
            }
        }
    }

    // rezero counts for the next graph replay (grid-stride)
    int stride = gridDim.x * blockDim.x;
    for (int i = blockIdx.x * blockDim.x + t; i < N_DST1; i += stride) g_cnt1[i] = 0;
    for (int i = blockIdx.x * blockDim.x + t; i < N_DST2; i += stride) g_cnt2[i] = 0;
}

// ---------------- launch ----------------
extern "C" void kernel_launch(void* const* d_in, const int* in_sizes, int n_in,
                              void* d_out, int out_size) {
    const float* x   = (const float*)d_in[0];
    const float* Ws1 = (const float*)d_in[1];
    const float* Wn1 = (const float*)d_in[2];
    const float* b1  = (const float*)d_in[3];
    const float* Ws2 = (const float*)d_in[4];
    const float* Wn2 = (const float*)d_in[5];
    const float* b2  = (const float*)d_in[6];
    const int* src1  = (const int*)d_in[7];
    const int* dst1  = (const int*)d_in[8];
    const int* src2  = (const int*)d_in[9];
    const int* dst2  = (const int*)d_in[10];
    float* out = (float*)d_out;

    static cudaStream_t s_side = nullptr;
    static cudaEvent_t ev_fork = nullptr, ev_join = nullptr;
    if (!s_side) {
        cudaStreamCreateWithFlags(&s_side, cudaStreamNonBlocking);
        cudaEventCreateWithFlags(&ev_fork, cudaEventDisableTiming);
        cudaEventCreateWithFlags(&ev_join, cudaEventDisableTiming);
    }

    dim3 g1(2, (N_DST1 + 127) / 128);

    // fork: side stream runs splitW + self-GEMM (depends only on x, Ws1, Wn1)
    cudaEventRecord(ev_fork, 0);
    cudaStreamWaitEvent(s_side, ev_fork, 0);
    k_splitW<<<256, 256, 0, s_side>>>(Ws1, Wn1);
    k_gemm1_self<<<g1, 256, 0, s_side>>>(x);
    cudaEventRecord(ev_join, s_side);

    // main stream: CSR build + neighbor aggregation (memory-bound)
    k_count<<<(E1 + 255) / 256, 256>>>(dst1, dst2);
    k_scanA<<<NB1 + NB2, 1024>>>();
    k_scanB<<<1, 256>>>();
    k_scanC<<<NB1 + NB2, 1024>>>();
    k_fill<<<(E1 + 255) / 256, 256>>>(src1, dst1, src2, dst2);
    k_agg1<<<(N_DST1 * 32 + 255) / 256, 256>>>((const float4*)x);

    // join, then neighbor half of layer-1 GEMM (reads partial g_h)
    cudaStreamWaitEvent(0, ev_join, 0);
    k_gemm1_neigh<<<g1, 256>>>(b1);

    k_agg2<<<(N_DST2 * 32 + 255) / 256, 256>>>();
    k_gemm2<<<(N_DST2 + 127) / 128, 256>>>(Ws2, Wn2, b2, out);
}

// round 10
// speedup vs baseline: 1.2380x; 1.2380x over previous
#include <cuda_runtime.h>
#include <cuda_bf16.h>
#include <cstring>
#include <cstdint>

#define N_SRC1 500000
#define N_DST1 100000
#define E1     1500000
#define N_DST2 20000
#define E2     200000
#define IN_F   128
#define H_F    256
#define N_CLS  47

#define NB1 98   // ceil(N_DST1/1024)
#define NB2 20   // ceil(N_DST2/1024)

// ---------------- scratch (device globals: no allocs allowed) ----------------
__device__ float g_hn1[(size_t)N_DST1 * IN_F];
__device__ float g_h[(size_t)N_DST1 * H_F];
__device__ float g_hn2[(size_t)N_DST2 * H_F];

__device__ __nv_bfloat16 g_Bhi[256 * 256];    // W1 split hi, [n][k]
__device__ __nv_bfloat16 g_Blo[256 * 256];    // W1 split lo, [n][k]
__device__ __nv_bfloat16 g_B2hi[48 * 512];    // W2 split hi, [n][k] (rows 47 = 0)
__device__ __nv_bfloat16 g_B2lo[48 * 512];    // W2 split lo, [n][k]

// zero-initialized at module load; re-zeroed by gemm2's tail every replay
__device__ int g_cnt1[N_DST1];
__device__ int g_cnt2[N_DST2];

__device__ int g_row1[N_DST1 + 1];
__device__ int g_cur1[N_DST1];
__device__ int g_eidx1[E1];

__device__ int g_row2[N_DST2 + 1];
__device__ int g_cur2[N_DST2];
__device__ int g_eidx2[E2];

__device__ int g_bsum1[128];
__device__ int g_bsum2[128];
__device__ int g_boff1[128];
__device__ int g_boff2[128];

// ---------------- helpers ----------------
__device__ __forceinline__ uint32_t sptr(const void* p) {
    return (uint32_t)__cvta_generic_to_shared(p);
}

__device__ __forceinline__ void split8(float4 v0, float4 v1, uint4& hi, uint4& lo) {
    float f[8] = {v0.x, v0.y, v0.z, v0.w, v1.x, v1.y, v1.z, v1.w};
    __nv_bfloat16 h[8], l[8];
    #pragma unroll
    for (int i = 0; i < 8; i++) {
        h[i] = __float2bfloat16_rn(f[i]);
        l[i] = __float2bfloat16_rn(f[i] - __bfloat162float(h[i]));
    }
    memcpy(&hi, h, 16);
    memcpy(&lo, l, 16);
}

__device__ __forceinline__ void ldm_x4(uint32_t* r, uint32_t addr) {
    asm volatile("ldmatrix.sync.aligned.m8n8.x4.shared.b16 {%0,%1,%2,%3}, [%4];"
                 : "=r"(r[0]), "=r"(r[1]), "=r"(r[2]), "=r"(r[3]) : "r"(addr));
}
__device__ __forceinline__ void ldm_x2(uint32_t* r, uint32_t addr) {
    asm volatile("ldmatrix.sync.aligned.m8n8.x2.shared.b16 {%0,%1}, [%2];"
                 : "=r"(r[0]), "=r"(r[1]) : "r"(addr));
}
__device__ __forceinline__ void mma16816(float* d, const uint32_t* a, uint32_t b0, uint32_t b1) {
    asm volatile(
        "mma.sync.aligned.m16n8k16.row.col.f32.bf16.bf16.f32 "
        "{%0,%1,%2,%3}, {%4,%5,%6,%7}, {%8,%9}, {%0,%1,%2,%3};"
        : "+f"(d[0]), "+f"(d[1]), "+f"(d[2]), "+f"(d[3])
        : "r"(a[0]), "r"(a[1]), "r"(a[2]), "r"(a[3]), "r"(b0), "r"(b1));
}

// ---------------- CSR counts + W1/W2 split (counts pre-zeroed) ----------------
__global__ void k_count_split(const int* __restrict__ d1, const int* __restrict__ d2,
                              const float* __restrict__ Ws1, const float* __restrict__ Wn1,
                              const float* __restrict__ Ws2, const float* __restrict__ Wn2) {
    int i = blockIdx.x * blockDim.x + threadIdx.x;
    if (i < 256 * 256) {   // W1: [k][n] fp32 -> [n][k] bf16 hi/lo
        int k = i >> 8;
        int n = i & 255;
        float w = (k < 128) ? Ws1[k * 256 + n] : Wn1[(k - 128) * 256 + n];
        __nv_bfloat16 h = __float2bfloat16_rn(w);
        __nv_bfloat16 l = __float2bfloat16_rn(w - __bfloat162float(h));
        g_Bhi[n * 256 + k] = h;
        g_Blo[n * 256 + k] = l;
    }
    if (i < 48 * 512) {    // W2: [k][47] fp32 -> [48][512] bf16 hi/lo (row 47 = 0)
        int n = i >> 9;
        int k = i & 511;
        float w = 0.f;
        if (n < N_CLS) w = (k < 256) ? Ws2[k * N_CLS + n] : Wn2[(k - 256) * N_CLS + n];
        __nv_bfloat16 h = __float2bfloat16_rn(w);
        __nv_bfloat16 l = __float2bfloat16_rn(w - __bfloat162float(h));
        g_B2hi[n * 512 + k] = h;
        g_B2lo[n * 512 + k] = l;
    }
    if (i < E1) atomicAdd(&g_cnt1[d1[i]], 1);
    if (i < E2) atomicAdd(&g_cnt2[d2[i]], 1);
}

__global__ void k_scanA() {
    __shared__ int s[1024];
    int b = blockIdx.x;
    const int* cnt; int n; int* bsum; int bb;
    if (b < NB1) { cnt = g_cnt1; n = N_DST1; bsum = g_bsum1; bb = b; }
    else         { cnt = g_cnt2; n = N_DST2; bsum = g_bsum2; bb = b - NB1; }
    int i = bb * 1024 + threadIdx.x;
    int v = (i < n) ? cnt[i] : 0;
    s[threadIdx.x] = v;
    __syncthreads();
    #pragma unroll
    for (int off = 512; off > 0; off >>= 1) {
        if (threadIdx.x < off) s[threadIdx.x] += s[threadIdx.x + off];
        __syncthreads();
    }
    if (threadIdx.x == 0) bsum[bb] = s[0];
}

__global__ void k_scanB() {
    __shared__ int s1[128];
    __shared__ int s2[128];
    int t = threadIdx.x;
    if (t < 128) s1[t] = (t < NB1) ? g_bsum1[t] : 0;
    else         { int u = t - 128; s2[u] = (u < NB2) ? g_bsum2[u] : 0; }
    __syncthreads();
    #pragma unroll
    for (int off = 1; off < 128; off <<= 1) {
        int v;
        if (t < 128) v = (t >= off) ? s1[t - off] : 0;
        else         { int u = t - 128; v = (u >= off) ? s2[u - off] : 0; }
        __syncthreads();
        if (t < 128) s1[t] += v;
        else         s2[t - 128] += v;
        __syncthreads();
    }
    if (t < 128) { if (t < NB1) g_boff1[t] = (t ? s1[t - 1] : 0); }
    else         { int u = t - 128; if (u < NB2) g_boff2[u] = (u ? s2[u - 1] : 0); }
}

__global__ void k_scanC() {
    __shared__ int s[1024];
    int b = blockIdx.x;
    const int* cnt; int n; int* row; int* cur; int boff; int bb; int etot;
    if (b < NB1) { cnt = g_cnt1; n = N_DST1; row = g_row1; cur = g_cur1; bb = b;       boff = g_boff1[bb]; etot = E1; }
    else         { cnt = g_cnt2; n = N_DST2; row = g_row2; cur = g_cur2; bb = b - NB1; boff = g_boff2[bb]; etot = E2; }
    int t = threadIdx.x;
    int i = bb * 1024 + t;
    int v = (i < n) ? cnt[i] : 0;
    s[t] = v;
    __syncthreads();
    #pragma unroll
    for (int off = 1; off < 1024; off <<= 1) {
        int u = (t >= off) ? s[t - off] : 0;
        __syncthreads();
        s[t] += u;
        __syncthreads();
    }
    int excl = boff + s[t] - v;
    if (i < n) { row[i] = excl; cur[i] = excl; }
    if (i == n - 1) row[n] = etot;
}

__global__ void k_fill(const int* __restrict__ s1, const int* __restrict__ d1,
                       const int* __restrict__ s2, const int* __restrict__ d2) {
    int i = blockIdx.x * blockDim.x + threadIdx.x;
    if (i < E1) {
        int p = atomicAdd(&g_cur1[d1[i]], 1);
        g_eidx1[p] = s1[i];
    }
    if (i < E2) {
        int p = atomicAdd(&g_cur2[d2[i]], 1);
        g_eidx2[p] = s2[i];
    }
}

// ---------------- aggregation (warp per dst node) ----------------
__global__ void k_agg1(const float4* __restrict__ x4) {
    int w = (blockIdx.x * blockDim.x + threadIdx.x) >> 5;
    int lane = threadIdx.x & 31;
    if (w >= N_DST1) return;
    int e0 = g_row1[w], e1 = g_row1[w + 1];
    float4 acc = make_float4(0.f, 0.f, 0.f, 0.f);
    int e = e0;
    for (; e + 3 < e1; e += 4) {
        int sa = g_eidx1[e];
        int sb = g_eidx1[e + 1];
        int sc = g_eidx1[e + 2];
        int sd = g_eidx1[e + 3];
        float4 va = __ldg(&x4[(size_t)sa * 32 + lane]);
        float4 vb = __ldg(&x4[(size_t)sb * 32 + lane]);
        float4 vc = __ldg(&x4[(size_t)sc * 32 + lane]);
        float4 vd = __ldg(&x4[(size_t)sd * 32 + lane]);
        acc.x += (va.x + vb.x) + (vc.x + vd.x);
        acc.y += (va.y + vb.y) + (vc.y + vd.y);
        acc.z += (va.z + vb.z) + (vc.z + vd.z);
        acc.w += (va.w + vb.w) + (vc.w + vd.w);
    }
    for (; e < e1; e++) {
        int sa = g_eidx1[e];
        float4 va = __ldg(&x4[(size_t)sa * 32 + lane]);
        acc.x += va.x; acc.y += va.y; acc.z += va.z; acc.w += va.w;
    }
    float inv = 1.0f / fmaxf((float)(e1 - e0), 1.0f);
    acc.x *= inv; acc.y *= inv; acc.z *= inv; acc.w *= inv;
    ((float4*)g_hn1)[(size_t)w * 32 + lane] = acc;
}

__global__ void k_agg2() {
    int w = (blockIdx.x * blockDim.x + threadIdx.x) >> 5;
    int lane = threadIdx.x & 31;
    if (w >= N_DST2) return;
    const float4* h4 = (const float4*)g_h;
    int e0 = g_row2[w], e1 = g_row2[w + 1];
    float4 a0 = make_float4(0.f, 0.f, 0.f, 0.f);
    float4 a1 = make_float4(0.f, 0.f, 0.f, 0.f);
    for (int e = e0; e < e1; e++) {
        int s = g_eidx2[e];
        float4 v0 = __ldg(&h4[(size_t)s * 64 + lane]);
        float4 v1 = __ldg(&h4[(size_t)s * 64 + lane + 32]);
        a0.x += v0.x; a0.y += v0.y; a0.z += v0.z; a0.w += v0.w;
        a1.x += v1.x; a1.y += v1.y; a1.z += v1.z; a1.w += v1.w;
    }
    float inv = 1.0f / fmaxf((float)(e1 - e0), 1.0f);
    a0.x *= inv; a0.y *= inv; a0.z *= inv; a0.w *= inv;
    a1.x *= inv; a1.y *= inv; a1.z *= inv; a1.w *= inv;
    ((float4*)g_hn2)[(size_t)w * 64 + lane] = a0;
    ((float4*)g_hn2)[(size_t)w * 64 + lane + 32] = a1;
}

// ---------------- layer-1 GEMM (tensor cores, bf16 hi/lo split) — round-6 proven ----------------
#define APITCH 24   // bf16 elements per smem row (16 data + 8 pad = 48B)

__global__ __launch_bounds__(256, 2) void k_gemm1(const float* __restrict__ x,
                                                  const float* __restrict__ b1) {
    __shared__ __nv_bfloat16 sAhi[128 * APITCH];
    __shared__ __nv_bfloat16 sAlo[128 * APITCH];
    __shared__ __nv_bfloat16 sBhi[128 * APITCH];
    __shared__ __nv_bfloat16 sBlo[128 * APITCH];

    int t = threadIdx.x;
    int lane = t & 31;
    int wid = t >> 5;
    int m0 = blockIdx.y * 128;
    int n0 = blockIdx.x * 128;
    int wm = (wid & 3) * 32;
    int wn = (wid >> 2) * 64;

    float acc[2][8][4];
    #pragma unroll
    for (int i = 0; i < 2; i++)
        #pragma unroll
        for (int j = 0; j < 8; j++)
            #pragma unroll
            for (int q = 0; q < 4; q++) acc[i][j][q] = 0.f;

    int lrow = t >> 1;
    int lq   = (t & 1) << 3;
    int grow = m0 + lrow;

    uint32_t aHi = sptr(sAhi), aLo = sptr(sAlo), bHi = sptr(sBhi), bLo = sptr(sBlo);
    int a_r = (lane & 15);
    int a_c = (lane >> 4) << 3;
    int b_r = (lane & 7) + ((lane >> 4) << 3);
    int b_c = ((lane >> 3) & 1) << 3;

    float4 pA0, pA1;
    uint4 pBh, pBl;

    auto ldA = [&](int kc) {
        const float* Ab = (kc < 8) ? (x + kc * 16) : (g_hn1 + (kc - 8) * 16);
        if (grow < N_DST1) {
            const float* p = Ab + (size_t)grow * IN_F + lq;
            pA0 = *(const float4*)p;
            pA1 = *(const float4*)(p + 4);
        } else {
            pA0 = make_float4(0.f, 0.f, 0.f, 0.f);
            pA1 = make_float4(0.f, 0.f, 0.f, 0.f);
        }
    };
    auto ldB = [&](int kc) {
        size_t off = (size_t)(n0 + lrow) * 256 + kc * 16 + lq;
        pBh = *(const uint4*)(g_Bhi + off);
        pBl = *(const uint4*)(g_Blo + off);
    };
    auto sts = [&]() {
        uint4 hi, lo;
        split8(pA0, pA1, hi, lo);
        *(uint4*)&sAhi[lrow * APITCH + lq] = hi;
        *(uint4*)&sAlo[lrow * APITCH + lq] = lo;
        *(uint4*)&sBhi[lrow * APITCH + lq] = pBh;
        *(uint4*)&sBlo[lrow * APITCH + lq] = pBl;
    };
    auto pass = [&](uint32_t abase, uint32_t bbase) {
        uint32_t a[2][4];
        #pragma unroll
        for (int mf = 0; mf < 2; mf++)
            ldm_x4(a[mf], abase + ((wm + mf * 16 + a_r) * APITCH + a_c) * 2);
        #pragma unroll
        for (int pair = 0; pair < 4; pair++) {
            uint32_t bb[4];
            ldm_x4(bb, bbase + ((wn + pair * 16 + b_r) * APITCH + b_c) * 2);
            #pragma unroll
            for (int mf = 0; mf < 2; mf++) {
                mma16816(acc[mf][pair * 2],     a[mf], bb[0], bb[1]);
                mma16816(acc[mf][pair * 2 + 1], a[mf], bb[2], bb[3]);
            }
        }
    };

    ldA(0);
    ldB(0);
    for (int kc = 0; kc < 16; kc++) {
        sts();
        __syncthreads();
        if (kc < 15) { ldA(kc + 1); ldB(kc + 1); }
        pass(aHi, bHi);
        pass(aLo, bHi);
        pass(aHi, bLo);
        __syncthreads();
    }

    #pragma unroll
    for (int mf = 0; mf < 2; mf++) {
        int gr0 = m0 + wm + mf * 16 + (lane >> 2);
        int gr1 = gr0 + 8;
        #pragma unroll
        for (int nf = 0; nf < 8; nf++) {
            int gn = n0 + wn + nf * 8 + ((lane & 3) << 1);
            float bx = b1[gn];
            float by = b1[gn + 1];
            float* d = acc[mf][nf];
            if (gr0 < N_DST1)
                *(float2*)&g_h[(size_t)gr0 * H_F + gn] =
                    make_float2(fmaxf(d[0] + bx, 0.f), fmaxf(d[1] + by, 0.f));
            if (gr1 < N_DST1)
                *(float2*)&g_h[(size_t)gr1 * H_F + gn] =
                    make_float2(fmaxf(d[2] + bx, 0.f), fmaxf(d[3] + by, 0.f));
        }
    }
}

// ---------------- layer-2 GEMM (tensor cores, bf16 hi/lo) + count-rezero tail ----------------
// out[20000,47] = [h|hn2] @ W2' + b2. Block 128 rows x 48 cols (N padded), K=512 in 32 chunks.
// 8 warps: 4m x 2n, warp tile 32x24 (2 m-frags, 3 n-octets: one ldm x4 + one ldm x2).
__global__ __launch_bounds__(256, 2) void k_gemm2(const float* __restrict__ b2,
                                                  float* __restrict__ out) {
    __shared__ __nv_bfloat16 sAhi[128 * APITCH];
    __shared__ __nv_bfloat16 sAlo[128 * APITCH];
    __shared__ __nv_bfloat16 sBhi[48 * APITCH];
    __shared__ __nv_bfloat16 sBlo[48 * APITCH];

    int t = threadIdx.x;
    int lane = t & 31;
    int wid = t >> 5;
    int m0 = blockIdx.x * 128;
    int wm = (wid & 3) * 32;
    int wn = (wid >> 2) * 24;

    float acc[2][3][4];
    #pragma unroll
    for (int i = 0; i < 2; i++)
        #pragma unroll
        for (int j = 0; j < 3; j++)
            #pragma unroll
            for (int q = 0; q < 4; q++) acc[i][j][q] = 0.f;

    int lrow = t >> 1;
    int lq   = (t & 1) << 3;
    int grow = m0 + lrow;

    uint32_t aHi = sptr(sAhi), aLo = sptr(sAlo), bHi = sptr(sBhi), bLo = sptr(sBlo);
    int a_r = (lane & 15);
    int a_c = (lane >> 4) << 3;
    int b_r = (lane & 7) + ((lane >> 4) << 3);
    int b_c = ((lane >> 3) & 1) << 3;
    int b2_r = lane & 7;                 // x2: rows wn+16..23
    int b2_c = ((lane >> 3) & 1) << 3;   // lanes 8-15 -> k8 (lanes 16-31 unused by x2)

    float4 pA0, pA1;
    uint4 pBq;   // B tile load: threads 0-95 hi, 96-191 lo

    auto ldA = [&](int kc) {   // kc 0..31; <16 from g_h, >=16 from g_hn2
        const float* Ab = (kc < 16) ? (g_h + kc * 16) : (g_hn2 + (kc - 16) * 16);
        if (grow < N_DST2) {
            const float* p = Ab + (size_t)grow * H_F + lq;
            pA0 = *(const float4*)p;
            pA1 = *(const float4*)(p + 4);
        } else {
            pA0 = make_float4(0.f, 0.f, 0.f, 0.f);
            pA1 = make_float4(0.f, 0.f, 0.f, 0.f);
        }
    };
    auto ldB = [&](int kc) {
        if (t < 192) {
            int idx = (t < 96) ? t : (t - 96);
            int row = idx >> 1;             // 0..47
            int half = (idx & 1) << 3;      // 0 or 8
            const __nv_bfloat16* src = (t < 96) ? g_B2hi : g_B2lo;
            pBq = *(const uint4*)(src + (size_t)row * 512 + kc * 16 + half);
        }
    };
    auto sts = [&]() {
        uint4 hi, lo;
        split8(pA0, pA1, hi, lo);
        *(uint4*)&sAhi[lrow * APITCH + lq] = hi;
        *(uint4*)&sAlo[lrow * APITCH + lq] = lo;
        if (t < 192) {
            int idx = (t < 96) ? t : (t - 96);
            int row = idx >> 1;
            int half = (idx & 1) << 3;
            __nv_bfloat16* dstp = (t < 96) ? sBhi : sBlo;
            *(uint4*)&dstp[row * APITCH + half] = pBq;
        }
    };
    auto pass = [&](uint32_t abase, uint32_t bbase) {
        uint32_t a[2][4];
        #pragma unroll
        for (int mf = 0; mf < 2; mf++)
            ldm_x4(a[mf], abase + ((wm + mf * 16 + a_r) * APITCH + a_c) * 2);
        uint32_t b4[4], bx2[2];
        ldm_x4(b4, bbase + ((wn + b_r) * APITCH + b_c) * 2);
        ldm_x2(bx2, bbase + ((wn + 16 + b2_r) * APITCH + b2_c) * 2);
        #pragma unroll
        for (int mf = 0; mf < 2; mf++) {
            mma16816(acc[mf][0], a[mf], b4[0], b4[1]);
            mma16816(acc[mf][1], a[mf], b4[2], b4[3]);
            mma16816(acc[mf][2], a[mf], bx2[0], bx2[1]);
        }
    };

    ldA(0);
    ldB(0);
    for (int kc = 0; kc < 32; kc++) {
        sts();
        __syncthreads();
        if (kc < 31) { ldA(kc + 1); ldB(kc + 1); }
        pass(aHi, bHi);
        pass(aLo, bHi);
        pass(aHi, bLo);
        __syncthreads();
    }

    // epilogue: bias, scalar guarded stores (out pitch 47 is odd)
    #pragma unroll
    for (int mf = 0; mf < 2; mf++) {
        int gr0 = m0 + wm + mf * 16 + (lane >> 2);
        int gr1 = gr0 + 8;
        #pragma unroll
        for (int nf = 0; nf < 3; nf++) {
            int gn = wn + nf * 8 + ((lane & 3) << 1);
            float* d = acc[mf][nf];
            if (gn < N_CLS) {
                float bx = b2[gn];
                if (gr0 < N_DST2) out[(size_t)gr0 * N_CLS + gn] = d[0] + bx;
                if (gr1 < N_DST2) out[(size_t)gr1 * N_CLS + gn] = d[2] + bx;
            }
            if (gn + 1 < N_CLS) {
                float by = b2[gn + 1];
                if (gr0 < N_DST2) out[(size_t)gr0 * N_CLS + gn + 1] = d[1] + by;
                if (gr1 < N_DST2) out[(size_t)gr1 * N_CLS + gn + 1] = d[3] + by;
            }
        }
    }

    // rezero counts for the next graph replay (grid-stride; 157 blocks x 256 thr)
    int stride = gridDim.x * blockDim.x;
    for (int i = blockIdx.x * blockDim.x + t; i < N_DST1; i += stride) g_cnt1[i] = 0;
    for (int i = blockIdx.x * blockDim.x + t; i < N_DST2; i += stride) g_cnt2[i] = 0;
}

// ---------------- launch ----------------
extern "C" void kernel_launch(void* const* d_in, const int* in_sizes, int n_in,
                              void* d_out, int out_size) {
    const float* x   = (const float*)d_in[0];
    const float* Ws1 = (const float*)d_in[1];
    const float* Wn1 = (const float*)d_in[2];
    const float* b1  = (const float*)d_in[3];
    const float* Ws2 = (const float*)d_in[4];
    const float* Wn2 = (const float*)d_in[5];
    const float* b2  = (const float*)d_in[6];
    const int* src1  = (const int*)d_in[7];
    const int* dst1  = (const int*)d_in[8];
    const int* src2  = (const int*)d_in[9];
    const int* dst2  = (const int*)d_in[10];
    float* out = (float*)d_out;

    k_count_split<<<(E1 + 255) / 256, 256>>>(dst1, dst2, Ws1, Wn1, Ws2, Wn2);  // 0
    k_scanA<<<NB1 + NB2, 1024>>>();                                            // 1
    k_scanB<<<1, 256>>>();                                                     // 2
    k_scanC<<<NB1 + NB2, 1024>>>();                                            // 3
    k_fill<<<(E1 + 255) / 256, 256>>>(src1, dst1, src2, dst2);                 // 4
    k_agg1<<<(N_DST1 * 32 + 255) / 256, 256>>>((const float4*)x);              // 5
    dim3 g1(2, (N_DST1 + 127) / 128);
    k_gemm1<<<g1, 256>>>(x, b1);                                               // 6
    k_agg2<<<(N_DST2 * 32 + 255) / 256, 256>>>();                              // 7
    k_gemm2<<<(N_DST2 + 127) / 128, 256>>>(b2, out);                           // 8
}